// round 4
// baseline (speedup 1.0000x reference)
#include <cuda_runtime.h>
#include <cstdint>

#define M_TOK 16
#define K_DIM 4096
#define N_OUT 11008
#define KT 256
#define TILES (K_DIM / KT)          // 16
#define O_PER_BLOCK 32
#define KSPLIT 8
#define BLOCK 256
#define XROW 20                     // 16 tokens + 4 pad (row 80B, 16B-aligned)
#define KPT (KT / KSPLIT)           // 32
#define WROW 260                    // 256 ints + 4 pad -> conflict-free LDS.128

#define X_ELEMS (M_TOK * K_DIM)
#define W_ELEMS ((long long)N_OUT * K_DIM)

// dynamic smem layout (bytes)
#define WBUF_OFF    0
#define WBUF_STRIDE (O_PER_BLOCK * WROW * 4)                    // 33280
#define XS_OFF      (2 * WBUF_STRIDE)                           // 66560
#define PART_OFF    (XS_OFF + KT * XROW * 4)                    // 87040
#define SUMX_OFF    (PART_OFF + O_PER_BLOCK * KSPLIT * M_TOK * 4) // 103424
#define MBAR_OFF    (SUMX_OFF + 64)                             // 103488
#define SMEM_TOTAL  (MBAR_OFF + 32)                             // 103520

__device__ __forceinline__ void ffma2(unsigned long long &d,
                                      unsigned long long a,
                                      unsigned long long b) {
    asm("fma.rn.f32x2 %0, %1, %2, %3;" : "=l"(d) : "l"(a), "l"(b), "l"(d));
}
__device__ __forceinline__ unsigned long long pack2(float v) {
    unsigned long long r;
    asm("mov.b64 %0, {%1, %1};" : "=l"(r) : "f"(v));
    return r;
}
__device__ __forceinline__ uint32_t smem_u32(const void* p) {
    uint32_t a;
    asm("{ .reg .u64 t; cvta.to.shared.u64 t, %1; cvt.u32.u64 %0, t; }"
        : "=r"(a) : "l"(p));
    return a;
}
__device__ __forceinline__ void mbar_init(uint32_t mbar, uint32_t cnt) {
    asm volatile("mbarrier.init.shared.b64 [%0], %1;" :: "r"(mbar), "r"(cnt) : "memory");
}
__device__ __forceinline__ void mbar_expect_tx(uint32_t mbar, uint32_t bytes) {
    asm volatile("mbarrier.arrive.expect_tx.shared.b64 _, [%0], %1;"
                 :: "r"(mbar), "r"(bytes) : "memory");
}
__device__ __forceinline__ void mbar_wait(uint32_t mbar, uint32_t parity) {
    uint32_t done;
    asm volatile(
        "{\n\t.reg .pred p;\n\t"
        "mbarrier.try_wait.parity.acquire.cta.shared::cta.b64 p, [%1], %2;\n\t"
        "selp.b32 %0, 1, 0, p;\n\t}"
        : "=r"(done) : "r"(mbar), "r"(parity) : "memory");
    if (!done) {
        asm volatile(
            "{\n\t.reg .pred P1;\n\t"
            "WL_%=:\n\t"
            "mbarrier.try_wait.parity.acquire.cta.shared::cta.b64 P1, [%0], %1, 0x989680;\n\t"
            "@P1 bra.uni WD_%=;\n\t"
            "bra.uni WL_%=;\n\t"
            "WD_%=:\n\t}"
            :: "r"(mbar), "r"(parity) : "memory");
    }
}
__device__ __forceinline__ void bulk_copy(uint32_t smem_dst, const void* gmem_src,
                                          uint32_t bytes, uint32_t mbar) {
    asm volatile(
        "cp.async.bulk.shared::cta.global.mbarrier::complete_tx::bytes "
        "[%0], [%1], %2, [%3];"
        :: "r"(smem_dst), "l"(gmem_src), "r"(bytes), "r"(mbar) : "memory");
}

__global__ void __launch_bounds__(BLOCK, 2)
qlin_kernel(const float* __restrict__ x,
            const int* __restrict__ w,        // weights marshaled as int32!
            const float* __restrict__ scale_p,
            const int* __restrict__ zp_p,
            float* __restrict__ out)
{
    extern __shared__ char smem[];
    const uint32_t sbase = smem_u32(smem);
    float* xs      = (float*)(smem + XS_OFF);
    float* partial = (float*)(smem + PART_OFF);
    float* sumx    = (float*)(smem + SUMX_OFF);
    const uint32_t mbar0 = sbase + MBAR_OFF;

    const int tid = threadIdx.x;
    const int o_local = tid & 31;
    const int ks = tid >> 5;
    const int o_base = blockIdx.x * O_PER_BLOCK;

    const int zp_val = *zp_p;
    if (zp_val != 0) {                 // exact path, not taken in this bench
        if (tid < M_TOK) {
            float s = 0.f;
            for (int k = 0; k < K_DIM; k++) s += x[tid * K_DIM + k];
            sumx[tid] = s;
        }
    }

    if (tid == 0) {
        mbar_init(mbar0 + 0, 1);
        mbar_init(mbar0 + 8, 1);
    }
    __syncthreads();

    // prologue: issue weight tiles 0 and 1 into the two buffers
    if (tid == 0) {
        #pragma unroll
        for (int b = 0; b < 2; b++) {
            mbar_expect_tx(mbar0 + b * 8, O_PER_BLOCK * KT * 4);
            for (int r = 0; r < O_PER_BLOCK; r++) {
                bulk_copy(sbase + WBUF_OFF + b * WBUF_STRIDE + r * WROW * 4,
                          w + (size_t)(o_base + r) * K_DIM + b * KT,
                          KT * 4, mbar0 + b * 8);
            }
        }
    }

    unsigned long long acc[8];
    #pragma unroll
    for (int i = 0; i < 8; i++) acc[i] = 0ULL;

    for (int t = 0; t < TILES; t++) {
        const int buf = t & 1;
        const uint32_t phase = (t >> 1) & 1;
        const int kt = t * KT;

        // ---- stage x tile transposed (conflict-free: lanes span tokens) ----
        // f = tid + i*256 in [0,1024): t_tok = f & 15, c4 = f >> 4 (0..63)
        #pragma unroll
        for (int i = 0; i < 4; i++) {
            int f = tid + i * BLOCK;
            int tt = f & 15;
            int c4 = f >> 4;
            float4 v = *(const float4*)(x + tt * K_DIM + kt + c4 * 4);
            int kk = c4 * 4;
            xs[(kk + 0) * XROW + tt] = v.x;
            xs[(kk + 1) * XROW + tt] = v.y;
            xs[(kk + 2) * XROW + tt] = v.z;
            xs[(kk + 3) * XROW + tt] = v.w;
        }
        __syncthreads();                 // xs ready for all warps

        mbar_wait(mbar0 + buf * 8, phase);   // weight tile landed

        // ---- compute: this thread covers KPT k values ----
        const int4* wp = (const int4*)((const int*)(smem + WBUF_OFF + buf * WBUF_STRIDE)
                                       + o_local * WROW + ks * KPT);
        #pragma unroll
        for (int v = 0; v < KPT / 4; v++) {      // 8 x LDS.128, conflict-free
            int4 q = wp[v];
            #pragma unroll
            for (int j = 0; j < 4; j++) {
                int iv = (j == 0) ? q.x : (j == 1) ? q.y : (j == 2) ? q.z : q.w;
                unsigned long long wf2 = pack2(__int2float_rn(iv));
                const float* xr = xs + (ks * KPT + v * 4 + j) * XROW;
                ulonglong2 p0 = *(const ulonglong2*)(xr + 0);
                ulonglong2 p1 = *(const ulonglong2*)(xr + 4);
                ulonglong2 p2 = *(const ulonglong2*)(xr + 8);
                ulonglong2 p3 = *(const ulonglong2*)(xr + 12);
                ffma2(acc[0], wf2, p0.x);
                ffma2(acc[1], wf2, p0.y);
                ffma2(acc[2], wf2, p1.x);
                ffma2(acc[3], wf2, p1.y);
                ffma2(acc[4], wf2, p2.x);
                ffma2(acc[5], wf2, p2.y);
                ffma2(acc[6], wf2, p3.x);
                ffma2(acc[7], wf2, p3.y);
            }
        }

        __syncthreads();                 // everyone done with wbuf[buf] & xs

        if (t + 2 < TILES && tid == 0) { // refill this buffer with tile t+2
            mbar_expect_tx(mbar0 + buf * 8, O_PER_BLOCK * KT * 4);
            for (int r = 0; r < O_PER_BLOCK; r++) {
                bulk_copy(sbase + WBUF_OFF + buf * WBUF_STRIDE + r * WROW * 4,
                          w + (size_t)(o_base + r) * K_DIM + (t + 2) * KT,
                          KT * 4, mbar0 + buf * 8);
            }
        }
    }

    // ---- reduce over KSPLIT through smem ----
    {
        float* pp = partial + (o_local * KSPLIT + ks) * M_TOK;
        #pragma unroll
        for (int i = 0; i < 8; i++) {
            float lo, hi;
            asm("mov.b64 {%0, %1}, %2;" : "=f"(lo), "=f"(hi) : "l"(acc[i]));
            pp[2 * i]     = lo;
            pp[2 * i + 1] = hi;
        }
    }
    __syncthreads();

    const float scale = *scale_p;
    const float zpf   = (float)zp_val;
    #pragma unroll
    for (int r = 0; r < 2; r++) {
        int idx = tid + r * BLOCK;       // 0..511
        int oo  = idx & 31;              // coalesced over o
        int tt  = idx >> 5;
        float s = 0.f;
        #pragma unroll
        for (int q = 0; q < KSPLIT; q++)
            s += partial[(oo * KSPLIT + q) * M_TOK + tt];
        if (zp_val != 0) s -= zpf * sumx[tt];
        out[tt * N_OUT + o_base + oo] = scale * s;
    }
}

extern "C" void kernel_launch(void* const* d_in, const int* in_sizes, int n_in,
                              void* d_out, int out_size) {
    const float* x  = nullptr;
    const int*   w  = nullptr;           // int8 weights are marshaled as int32
    const float* sc = nullptr;
    const int*   zp = nullptr;
    for (int i = 0; i < n_in; i++) {
        long long n = in_sizes[i];
        if (n == W_ELEMS)       w = (const int*)d_in[i];
        else if (n == X_ELEMS)  x = (const float*)d_in[i];
        else if (!sc)           sc = (const float*)d_in[i];
        else                    zp = (const int*)d_in[i];
    }
    (void)out_size;
    static bool attr_set = false;
    if (!attr_set) {
        cudaFuncSetAttribute(qlin_kernel,
                             cudaFuncAttributeMaxDynamicSharedMemorySize, SMEM_TOTAL);
        attr_set = true;
    }
    qlin_kernel<<<N_OUT / O_PER_BLOCK, BLOCK, SMEM_TOTAL>>>(x, w, sc, zp, (float*)d_out);
}

// round 6
// speedup vs baseline: 1.4414x; 1.4414x over previous
#include <cuda_runtime.h>
#include <cstdint>

#define M_TOK   16
#define K_DIM   4096
#define N_OUT   11008
#define OTILE   32
#define NCTA    (N_OUT / OTILE)     // 344
#define KT      128                 // k per stage
#define SCNT    (K_DIM / KT)        // 32 stages
#define THREADS 256
#define KSPLIT  8                   // 8 warps split the 128 k of a stage
#define KPW     (KT / KSPLIT)       // 16 k per warp per stage

#define XROW_B  80                  // 16 tok * 4B + 16B pad (TMA-contiguous rows)
#define WSTRIDE 528                 // 512B row + 16B pad (conflict-free LDS.128)
#define W_REGION (OTILE * WSTRIDE)  // 16896
#define X_REGION (KT * XROW_B)      // 10240
#define ST_SIZE  (W_REGION + X_REGION)  // 27136
#define MBAR_OFF (2 * ST_SIZE)          // 54272
#define TX_BYTES (OTILE * (KT * 4) + X_REGION)  // 16384 + 10240 = 26624
#define DYN_SMEM (MBAR_OFF + 16)

#define X_ELEMS (M_TOK * K_DIM)
#define W_ELEMS ((long long)N_OUT * K_DIM)

static __device__ __align__(16) float g_xT[K_DIM * 20];   // transposed, padded x
static __device__ float g_sumx[M_TOK];

__device__ __forceinline__ void ffma2(unsigned long long &d,
                                      unsigned long long a,
                                      unsigned long long b) {
    asm("fma.rn.f32x2 %0, %1, %2, %3;" : "=l"(d) : "l"(a), "l"(b), "l"(d));
}
__device__ __forceinline__ unsigned long long pack2(float v) {
    unsigned long long r;
    asm("mov.b64 %0, {%1, %1};" : "=l"(r) : "f"(v));
    return r;
}
__device__ __forceinline__ uint32_t smem_u32(const void* p) {
    uint32_t a;
    asm("{ .reg .u64 t; cvta.to.shared.u64 t, %1; cvt.u32.u64 %0, t; }"
        : "=r"(a) : "l"(p));
    return a;
}
__device__ __forceinline__ void mbar_init(uint32_t mbar, uint32_t cnt) {
    asm volatile("mbarrier.init.shared.b64 [%0], %1;" :: "r"(mbar), "r"(cnt) : "memory");
}
__device__ __forceinline__ void mbar_expect_tx(uint32_t mbar, uint32_t bytes) {
    asm volatile("mbarrier.arrive.expect_tx.shared.b64 _, [%0], %1;"
                 :: "r"(mbar), "r"(bytes) : "memory");
}
__device__ __forceinline__ void mbar_wait(uint32_t mbar, uint32_t parity) {
    uint32_t done;
    asm volatile(
        "{\n\t.reg .pred p;\n\t"
        "mbarrier.try_wait.parity.acquire.cta.shared::cta.b64 p, [%1], %2;\n\t"
        "selp.b32 %0, 1, 0, p;\n\t}"
        : "=r"(done) : "r"(mbar), "r"(parity) : "memory");
    if (!done) {
        asm volatile(
            "{\n\t.reg .pred P1;\n\t"
            "WL_%=:\n\t"
            "mbarrier.try_wait.parity.acquire.cta.shared::cta.b64 P1, [%0], %1, 0x989680;\n\t"
            "@P1 bra.uni WD_%=;\n\t"
            "bra.uni WL_%=;\n\t"
            "WD_%=:\n\t}"
            :: "r"(mbar), "r"(parity) : "memory");
    }
}
__device__ __forceinline__ void bulk_copy(uint32_t smem_dst, const void* gmem_src,
                                          uint32_t bytes, uint32_t mbar) {
    asm volatile(
        "cp.async.bulk.shared::cta.global.mbarrier::complete_tx::bytes "
        "[%0], [%1], %2, [%3];"
        :: "r"(smem_dst), "l"(gmem_src), "r"(bytes), "r"(mbar) : "memory");
}

// ---------------- prep: transpose x (padded rows), row sums ----------------
__global__ void prep_kernel(const float* __restrict__ x) {
    int t = blockIdx.x;              // token 0..15
    int tid = threadIdx.x;           // 256
    __shared__ float red[256];
    float s = 0.f;
    for (int k = tid; k < K_DIM; k += 256) {
        float v = x[t * K_DIM + k];
        g_xT[k * 20 + t] = v;
        s += v;
    }
    red[tid] = s;
    __syncthreads();
    for (int st = 128; st > 0; st >>= 1) {
        if (tid < st) red[tid] += red[tid + st];
        __syncthreads();
    }
    if (tid == 0) g_sumx[t] = red[0];
}

// ---------------- main: TMA-fed f32x2 GEMV-ish GEMM -------------------------
__global__ void __launch_bounds__(THREADS, 3)
gemm_kernel(const int* __restrict__ w,          // int8 marshaled as int32
            const float* __restrict__ scale_p,
            const int* __restrict__ zp_p,
            float* __restrict__ out)
{
    extern __shared__ __align__(16) char smem[];
    const uint32_t sbase = smem_u32(smem);
    const uint32_t mbar0 = sbase + MBAR_OFF;

    const int tid  = threadIdx.x;
    const int ks   = tid >> 5;       // warp = k-split index
    const int lane = tid & 31;       // lane = output row
    const int o_base = blockIdx.x * OTILE;

    if (tid == 0) {
        mbar_init(mbar0 + 0, 1);
        mbar_init(mbar0 + 8, 1);
    }
    __syncthreads();

    // prologue: issue stages 0 and 1
    #pragma unroll
    for (int s = 0; s < 2; s++) {
        const uint32_t mb = mbar0 + s * 8;
        if (tid == 0) mbar_expect_tx(mb, TX_BYTES);
        if (tid < OTILE)
            bulk_copy(sbase + s * ST_SIZE + tid * WSTRIDE,
                      w + (size_t)(o_base + tid) * K_DIM + s * KT,
                      KT * 4, mb);
        else if (tid == OTILE)
            bulk_copy(sbase + s * ST_SIZE + W_REGION,
                      g_xT + s * KT * 20, X_REGION, mb);
    }

    unsigned long long acc[8];
    #pragma unroll
    for (int i = 0; i < 8; i++) acc[i] = 0ULL;

    for (int s = 0; s < SCNT; s++) {
        const int buf = s & 1;
        const uint32_t phase = (s >> 1) & 1;
        mbar_wait(mbar0 + buf * 8, phase);

        // this warp's slice: k in [ks*16, ks*16+16) of the stage
        const char* wb = smem + buf * ST_SIZE + lane * WSTRIDE + ks * (KPW * 4);
        const char* xb = smem + buf * ST_SIZE + W_REGION + ks * (KPW * XROW_B);

        #pragma unroll
        for (int j = 0; j < KPW / 4; j++) {        // 4 int4 = 16 k
            int4 q = *(const int4*)(wb + j * 16);
            #pragma unroll
            for (int u = 0; u < 4; u++) {
                int iv = (u == 0) ? q.x : (u == 1) ? q.y : (u == 2) ? q.z : q.w;
                unsigned long long wf2 = pack2(__int2float_rn(iv));
                const char* xr = xb + (j * 4 + u) * XROW_B;
                ulonglong2 p0 = *(const ulonglong2*)(xr +  0);  // t0..3
                ulonglong2 p1 = *(const ulonglong2*)(xr + 16);  // t4..7
                ulonglong2 p2 = *(const ulonglong2*)(xr + 32);  // t8..11
                ulonglong2 p3 = *(const ulonglong2*)(xr + 48);  // t12..15
                ffma2(acc[0], wf2, p0.x);
                ffma2(acc[1], wf2, p0.y);
                ffma2(acc[2], wf2, p1.x);
                ffma2(acc[3], wf2, p1.y);
                ffma2(acc[4], wf2, p2.x);
                ffma2(acc[5], wf2, p2.y);
                ffma2(acc[6], wf2, p3.x);
                ffma2(acc[7], wf2, p3.y);
            }
        }

        __syncthreads();                 // whole CTA done with buf

        if (s + 2 < SCNT) {              // refill buf with stage s+2
            const uint32_t mb = mbar0 + buf * 8;
            if (tid == 0) mbar_expect_tx(mb, TX_BYTES);
            if (tid < OTILE)
                bulk_copy(sbase + buf * ST_SIZE + tid * WSTRIDE,
                          w + (size_t)(o_base + tid) * K_DIM + (s + 2) * KT,
                          KT * 4, mb);
            else if (tid == OTILE)
                bulk_copy(sbase + buf * ST_SIZE + W_REGION,
                          g_xT + (s + 2) * KT * 20, X_REGION, mb);
        }
    }

    // ---- reduce over KSPLIT through smem (reuse stage memory) ----
    float* part = (float*)smem;          // [(o*8+ks)*17 + t], 17408B
    {
        float* pp = part + (lane * KSPLIT + ks) * 17;
        #pragma unroll
        for (int i = 0; i < 8; i++) {
            float lo, hi;
            asm("mov.b64 {%0, %1}, %2;" : "=f"(lo), "=f"(hi) : "l"(acc[i]));
            pp[2 * i]     = lo;
            pp[2 * i + 1] = hi;
        }
    }
    __syncthreads();

    const float scale = *scale_p;
    const float zpf   = (float)(*zp_p);
    #pragma unroll
    for (int r = 0; r < 2; r++) {
        int idx = tid + r * THREADS;     // 0..511
        int oo  = idx & 31;              // coalesced over o
        int tt  = idx >> 5;
        float v = 0.f;
        #pragma unroll
        for (int q = 0; q < KSPLIT; q++)
            v += part[(oo * KSPLIT + q) * 17 + tt];
        out[(size_t)tt * N_OUT + o_base + oo] = scale * (v - zpf * g_sumx[tt]);
    }
}

extern "C" void kernel_launch(void* const* d_in, const int* in_sizes, int n_in,
                              void* d_out, int out_size) {
    const float* x  = nullptr;
    const int*   w  = nullptr;           // int8 weights marshaled as int32
    const float* sc = nullptr;
    const int*   zp = nullptr;
    for (int i = 0; i < n_in; i++) {
        long long n = in_sizes[i];
        if (n == W_ELEMS)       w  = (const int*)d_in[i];
        else if (n == X_ELEMS)  x  = (const float*)d_in[i];
        else if (!sc)           sc = (const float*)d_in[i];
        else                    zp = (const int*)d_in[i];
    }
    (void)out_size;
    static bool attr_set = false;
    if (!attr_set) {
        cudaFuncSetAttribute(gemm_kernel,
                             cudaFuncAttributeMaxDynamicSharedMemorySize, DYN_SMEM);
        attr_set = true;
    }
    prep_kernel<<<M_TOK, 256>>>(x);
    gemm_kernel<<<NCTA, THREADS, DYN_SMEM>>>(w, sc, zp, (float*)d_out);
}

// round 7
// speedup vs baseline: 1.5641x; 1.0851x over previous
#include <cuda_runtime.h>
#include <cuda.h>
#include <cstdint>

#define M_TOK   16
#define K_DIM   4096
#define N_OUT   11008
#define OTILE   32
#define NCTA    (N_OUT / OTILE)     // 344
#define KT      128                 // k per stage
#define SCNT    (K_DIM / KT)        // 32 stages
#define THREADS 256
#define KSPLIT  8
#define KPW     (KT / KSPLIT)       // 16

#define XROW_B  80                  // 16 tok * 4B + 16B pad
#define WBOX0   132                 // 128 k ints + 4 pad ints (TMA box inner dim)
#define WSTRIDE (WBOX0 * 4)         // 528 B row pitch -> conflict-free LDS.128
#define W_REGION (OTILE * WSTRIDE)  // 16896
#define X_REGION (KT * XROW_B)      // 10240
#define ST_SIZE  (W_REGION + X_REGION)  // 27136
#define MBAR_OFF (2 * ST_SIZE)          // 54272
#define TX_BYTES ST_SIZE
#define DYN_SMEM (MBAR_OFF + 16)        // 54288

#define X_ELEMS (M_TOK * K_DIM)
#define W_ELEMS ((long long)N_OUT * K_DIM)

static __device__ __align__(16) float g_xT[K_DIM * 20];   // transposed, padded x
static __device__ float g_psum[M_TOK * 8];
static __device__ float g_sumx[M_TOK];

__device__ __forceinline__ void ffma2(unsigned long long &d,
                                      unsigned long long a,
                                      unsigned long long b) {
    asm("fma.rn.f32x2 %0, %1, %2, %3;" : "=l"(d) : "l"(a), "l"(b), "l"(d));
}
__device__ __forceinline__ unsigned long long pack2(float v) {
    unsigned long long r;
    asm("mov.b64 %0, {%1, %1};" : "=l"(r) : "f"(v));
    return r;
}
__device__ __forceinline__ uint32_t smem_u32(const void* p) {
    uint32_t a;
    asm("{ .reg .u64 t; cvta.to.shared.u64 t, %1; cvt.u32.u64 %0, t; }"
        : "=r"(a) : "l"(p));
    return a;
}
__device__ __forceinline__ void mbar_init(uint32_t mbar, uint32_t cnt) {
    asm volatile("mbarrier.init.shared.b64 [%0], %1;" :: "r"(mbar), "r"(cnt) : "memory");
}
__device__ __forceinline__ void mbar_expect_tx(uint32_t mbar, uint32_t bytes) {
    asm volatile("mbarrier.arrive.expect_tx.shared.b64 _, [%0], %1;"
                 :: "r"(mbar), "r"(bytes) : "memory");
}
__device__ __forceinline__ void mbar_wait(uint32_t mbar, uint32_t parity) {
    uint32_t done;
    asm volatile(
        "{\n\t.reg .pred p;\n\t"
        "mbarrier.try_wait.parity.acquire.cta.shared::cta.b64 p, [%1], %2;\n\t"
        "selp.b32 %0, 1, 0, p;\n\t}"
        : "=r"(done) : "r"(mbar), "r"(parity) : "memory");
    if (!done) {
        asm volatile(
            "{\n\t.reg .pred P1;\n\t"
            "WL_%=:\n\t"
            "mbarrier.try_wait.parity.acquire.cta.shared::cta.b64 P1, [%0], %1, 0x989680;\n\t"
            "@P1 bra.uni WD_%=;\n\t"
            "bra.uni WL_%=;\n\t"
            "WD_%=:\n\t}"
            :: "r"(mbar), "r"(parity) : "memory");
    }
}
__device__ __forceinline__ void bulk_copy(uint32_t smem_dst, const void* gmem_src,
                                          uint32_t bytes, uint32_t mbar) {
    asm volatile(
        "cp.async.bulk.shared::cta.global.mbarrier::complete_tx::bytes "
        "[%0], [%1], %2, [%3];"
        :: "r"(smem_dst), "l"(gmem_src), "r"(bytes), "r"(mbar) : "memory");
}
__device__ __forceinline__ void tma_load_2d(uint32_t smem_dst, const void* tmap,
                                            int cx, int cy, uint32_t mbar) {
    asm volatile(
        "cp.async.bulk.tensor.2d.shared::cta.global.tile.mbarrier::complete_tx::bytes "
        "[%0], [%1, {%2, %3}], [%4];"
        :: "r"(smem_dst), "l"(tmap), "r"(cx), "r"(cy), "r"(mbar) : "memory");
}

// ---------------- prep: transpose x (padded rows), partial row sums ----------
__global__ void prep1_kernel(const float* __restrict__ x) {
    const int t = blockIdx.x & 15;          // token
    const int c = blockIdx.x >> 4;          // k-chunk 0..7
    const int tid = threadIdx.x;            // 256
    __shared__ float red[256];
    float s = 0.f;
    #pragma unroll
    for (int i = 0; i < 2; i++) {
        int k = c * 512 + tid + i * 256;
        float v = x[t * K_DIM + k];
        g_xT[k * 20 + t] = v;
        s += v;
    }
    red[tid] = s;
    __syncthreads();
    for (int st = 128; st > 0; st >>= 1) {
        if (tid < st) red[tid] += red[tid + st];
        __syncthreads();
    }
    if (tid == 0) g_psum[t * 8 + c] = red[0];
}
__global__ void prep2_kernel() {
    int t = threadIdx.x;
    if (t < M_TOK) {
        float s = 0.f;
        #pragma unroll
        for (int c = 0; c < 8; c++) s += g_psum[t * 8 + c];
        g_sumx[t] = s;
    }
}

// ---------------- main: single-request TMA 2D weight tiles ------------------
__global__ void __launch_bounds__(THREADS, 3)
gemm_kernel(const __grid_constant__ CUtensorMap wmap,
            const float* __restrict__ scale_p,
            const int* __restrict__ zp_p,
            float* __restrict__ out)
{
    extern __shared__ __align__(16) char smem[];
    const uint32_t sbase = smem_u32(smem);
    const uint32_t mbar0 = sbase + MBAR_OFF;

    const int tid  = threadIdx.x;
    const int ks   = tid >> 5;       // warp = k-split index
    const int lane = tid & 31;       // lane = output row
    const int o_base = blockIdx.x * OTILE;

    if (tid == 0) {
        mbar_init(mbar0 + 0, 1);
        mbar_init(mbar0 + 8, 1);
    }
    __syncthreads();

    // prologue: issue stages 0 and 1 (2 requests each: w-tile + x-chunk)
    if (tid == 0) {
        #pragma unroll
        for (int s = 0; s < 2; s++) {
            const uint32_t mb = mbar0 + s * 8;
            mbar_expect_tx(mb, TX_BYTES);
            tma_load_2d(sbase + s * ST_SIZE, &wmap, s * KT, o_base, mb);
            bulk_copy(sbase + s * ST_SIZE + W_REGION,
                      g_xT + s * KT * 20, X_REGION, mb);
        }
    }

    unsigned long long acc[8];
    #pragma unroll
    for (int i = 0; i < 8; i++) acc[i] = 0ULL;

    for (int s = 0; s < SCNT; s++) {
        const int buf = s & 1;
        const uint32_t phase = (s >> 1) & 1;
        mbar_wait(mbar0 + buf * 8, phase);

        const char* wb = smem + buf * ST_SIZE + lane * WSTRIDE + ks * (KPW * 4);
        const char* xb = smem + buf * ST_SIZE + W_REGION + ks * (KPW * XROW_B);

        #pragma unroll
        for (int j = 0; j < KPW / 4; j++) {
            int4 q = *(const int4*)(wb + j * 16);
            #pragma unroll
            for (int u = 0; u < 4; u++) {
                int iv = (u == 0) ? q.x : (u == 1) ? q.y : (u == 2) ? q.z : q.w;
                // exact dequant: |iv| <= 127 fits the magic mantissa window
                float wf = __int_as_float(iv + 0x4B400000) - 12582912.0f;
                unsigned long long wf2 = pack2(wf);
                const char* xr = xb + (j * 4 + u) * XROW_B;
                ulonglong2 p0 = *(const ulonglong2*)(xr +  0);
                ulonglong2 p1 = *(const ulonglong2*)(xr + 16);
                ulonglong2 p2 = *(const ulonglong2*)(xr + 32);
                ulonglong2 p3 = *(const ulonglong2*)(xr + 48);
                ffma2(acc[0], wf2, p0.x);
                ffma2(acc[1], wf2, p0.y);
                ffma2(acc[2], wf2, p1.x);
                ffma2(acc[3], wf2, p1.y);
                ffma2(acc[4], wf2, p2.x);
                ffma2(acc[5], wf2, p2.y);
                ffma2(acc[6], wf2, p3.x);
                ffma2(acc[7], wf2, p3.y);
            }
        }

        __syncthreads();                 // whole CTA done with buf

        if (s + 2 < SCNT && tid == 0) {  // refill buf with stage s+2
            const uint32_t mb = mbar0 + buf * 8;
            mbar_expect_tx(mb, TX_BYTES);
            tma_load_2d(sbase + buf * ST_SIZE, &wmap, (s + 2) * KT, o_base, mb);
            bulk_copy(sbase + buf * ST_SIZE + W_REGION,
                      g_xT + (s + 2) * KT * 20, X_REGION, mb);
        }
    }

    // ---- reduce over KSPLIT through smem (reuse stage memory) ----
    float* part = (float*)smem;          // [(o*8+ks)*17 + t]
    {
        float* pp = part + (lane * KSPLIT + ks) * 17;
        #pragma unroll
        for (int i = 0; i < 8; i++) {
            float lo, hi;
            asm("mov.b64 {%0, %1}, %2;" : "=f"(lo), "=f"(hi) : "l"(acc[i]));
            pp[2 * i]     = lo;
            pp[2 * i + 1] = hi;
        }
    }
    __syncthreads();

    const float scale = *scale_p;
    const float zpf   = (float)(*zp_p);
    #pragma unroll
    for (int r = 0; r < 2; r++) {
        int idx = tid + r * THREADS;     // 0..511
        int oo  = idx & 31;
        int tt  = idx >> 5;
        float v = 0.f;
        #pragma unroll
        for (int q = 0; q < KSPLIT; q++)
            v += part[(oo * KSPLIT + q) * 17 + tt];
        out[(size_t)tt * N_OUT + o_base + oo] = scale * (v - zpf * g_sumx[tt]);
    }
}

// ---------------- host ----------------
typedef CUresult (*EncodeTiledFn)(
    CUtensorMap*, CUtensorMapDataType, cuuint32_t, void*,
    const cuuint64_t*, const cuuint64_t*, const cuuint32_t*, const cuuint32_t*,
    CUtensorMapInterleave, CUtensorMapSwizzle, CUtensorMapL2promotion,
    CUtensorMapFloatOOBfill);

static EncodeTiledFn get_encode_fn() {
    static EncodeTiledFn fn = nullptr;
    if (fn) return fn;
    void* p = nullptr;
#if CUDART_VERSION >= 12050
    cudaDriverEntryPointQueryResult st;
    if (cudaGetDriverEntryPointByVersion("cuTensorMapEncodeTiled", &p, 12000,
                                         cudaEnableDefault, &st) != cudaSuccess)
        p = nullptr;
#endif
    if (!p) {
        cudaDriverEntryPointQueryResult st2;
        cudaGetDriverEntryPoint("cuTensorMapEncodeTiled", &p,
                                cudaEnableDefault, &st2);
    }
    fn = (EncodeTiledFn)p;
    return fn;
}

extern "C" void kernel_launch(void* const* d_in, const int* in_sizes, int n_in,
                              void* d_out, int out_size) {
    const float* x  = nullptr;
    const int*   w  = nullptr;           // int8 weights marshaled as int32
    const float* sc = nullptr;
    const int*   zp = nullptr;
    for (int i = 0; i < n_in; i++) {
        long long n = in_sizes[i];
        if (n == W_ELEMS)       w  = (const int*)d_in[i];
        else if (n == X_ELEMS)  x  = (const float*)d_in[i];
        else if (!sc)           sc = (const float*)d_in[i];
        else                    zp = (const int*)d_in[i];
    }
    (void)out_size;

    static bool attr_set = false;
    if (!attr_set) {
        cudaFuncSetAttribute(gemm_kernel,
                             cudaFuncAttributeMaxDynamicSharedMemorySize, DYN_SMEM);
        attr_set = true;
    }

    // Encode 2D tensor map for W: [dim0 = K (int32 elems), dim1 = rows]
    CUtensorMap wmap;
    {
        EncodeTiledFn enc = get_encode_fn();
        cuuint64_t dims[2]    = {(cuuint64_t)K_DIM, (cuuint64_t)N_OUT};
        cuuint64_t strides[1] = {(cuuint64_t)K_DIM * 4};
        cuuint32_t box[2]     = {(cuuint32_t)WBOX0, (cuuint32_t)OTILE};
        cuuint32_t estr[2]    = {1, 1};
        enc(&wmap, CU_TENSOR_MAP_DATA_TYPE_UINT32, 2, (void*)w,
            dims, strides, box, estr,
            CU_TENSOR_MAP_INTERLEAVE_NONE, CU_TENSOR_MAP_SWIZZLE_NONE,
            CU_TENSOR_MAP_L2_PROMOTION_L2_128B,
            CU_TENSOR_MAP_FLOAT_OOB_FILL_NONE);
    }

    prep1_kernel<<<128, 256>>>(x);
    prep2_kernel<<<1, 32>>>();
    gemm_kernel<<<NCTA, THREADS, DYN_SMEM>>>(wmap, sc, zp, (float*)d_out);
}